// round 15
// baseline (speedup 1.0000x reference)
#include <cuda_runtime.h>
#include <cuda_fp16.h>
#include <math.h>

#define NBATCH 4096
#define TWO_N  8192
#define DIMK   256
#define INV_TEMP 2.0f
#define QSCALE 16.0f            // fp8 quantization scale
#define EPSCL  (2.0f / 256.0f)  // epilogue: INV_TEMP / QSCALE^2

// ---------------- device scratch (no allocs allowed) ----------------
__device__ unsigned char g_fp8[TWO_N * DIMK]; // normalized reps e4m3*16 (2 MB)
__device__ float    g_pos[TWO_N];             // positive-pair cosine (fp32 exact)
__device__ float    g_rowsum[TWO_N];          // atomically accumulated row sums
__device__ float    g_partial[32];            // finalize partials
__device__ unsigned g_ctr;                    // last-block-done counter

// ---------------- PTX helpers (base sm_103 target only) ----------------
static __device__ __forceinline__ unsigned smem_u32(const void* p) {
    unsigned a;
    asm("{ .reg .u64 t; cvta.to.shared.u64 t, %1; cvt.u32.u64 %0, t; }" : "=r"(a) : "l"(p));
    return a;
}

// pack two f32 -> e4m3x2 (lo in low byte)
static __device__ __forceinline__ unsigned short pk_e4m3(float lo, float hi) {
    unsigned short r;
    asm("cvt.rn.satfinite.e4m3x2.f32 %0, %2, %1;" : "=h"(r) : "f"(lo), "f"(hi));
    return r;
}

#define CP_ASYNC16(dst, src) \
    asm volatile("cp.async.cg.shared.global [%0], [%1], 16;" :: "r"(dst), "l"(src) : "memory")
#define CP_ASYNC_COMMIT() asm volatile("cp.async.commit_group;" ::: "memory")

#define LDSM_X4(r0, r1, r2, r3, addr) \
    asm volatile("ldmatrix.sync.aligned.m8n8.x4.shared.b16 {%0,%1,%2,%3}, [%4];" \
        : "=r"(r0), "=r"(r1), "=r"(r2), "=r"(r3) : "r"(addr))

// fp8 e4m3 MMA: m16n8k32, f16 accumulate
#define MMA_FP8_H(c01, c23, a0, a1, a2, a3, b0, b1) \
    asm volatile("mma.sync.aligned.m16n8k32.row.col.f16.e4m3.e4m3.f16 " \
        "{%0,%1}, {%2,%3,%4,%5}, {%6,%7}, {%0,%1};" \
        : "+r"(c01), "+r"(c23) \
        : "r"(a0), "r"(a1), "r"(a2), "r"(a3), "r"(b0), "r"(b1))

// ---------------- kernel 1: normalize + positive pairs -> fp8 ----------------
// 2 warps per pair (each owns 128 of 256 dims); grid 1024 x 256 -> 8192 warps.
__global__ void ntx_norm(const float* __restrict__ zis,
                         const float* __restrict__ zjs) {
    __shared__ float sred[4][2][3];
    int tid = threadIdx.x, wid = tid >> 5, lane = tid & 31;
    if (blockIdx.x == 0 && tid == 0) g_ctr = 0;
    if (blockIdx.x < 32) g_rowsum[blockIdx.x * 256 + tid] = 0.0f;

    int pl = wid >> 1, half = wid & 1;
    int p = blockIdx.x * 4 + pl;
    const float4* j4 = (const float4*)(zjs + (size_t)p * DIMK) + half * 32;
    const float4* i4 = (const float4*)(zis + (size_t)p * DIMK) + half * 32;
    float4 jv = j4[lane], iv = i4[lane];
    float ssj = jv.x*jv.x + jv.y*jv.y + jv.z*jv.z + jv.w*jv.w;
    float ssi = iv.x*iv.x + iv.y*iv.y + iv.z*iv.z + iv.w*iv.w;
    float dot = jv.x*iv.x + jv.y*iv.y + jv.z*iv.z + jv.w*iv.w;
    #pragma unroll
    for (int o = 16; o >= 1; o >>= 1) {
        ssj += __shfl_xor_sync(0xFFFFFFFFu, ssj, o);
        ssi += __shfl_xor_sync(0xFFFFFFFFu, ssi, o);
        dot += __shfl_xor_sync(0xFFFFFFFFu, dot, o);
    }
    if (lane == 0) {
        sred[pl][half][0] = ssj;
        sred[pl][half][1] = ssi;
        sred[pl][half][2] = dot;
    }
    __syncthreads();
    float tssj = sred[pl][0][0] + sred[pl][1][0];
    float tssi = sred[pl][0][1] + sred[pl][1][1];
    float tdot = sred[pl][0][2] + sred[pl][1][2];
    float rj = rsqrtf(tssj), ri = rsqrtf(tssi);
    float rnj = rj * QSCALE, rni = ri * QSCALE;

    unsigned* dj = (unsigned*)(g_fp8 + (size_t)p * DIMK);
    unsigned* di = (unsigned*)(g_fp8 + (size_t)(p + NBATCH) * DIMK);
    int w = half * 32 + lane;
    dj[w] = (unsigned)pk_e4m3(jv.x*rnj, jv.y*rnj) | ((unsigned)pk_e4m3(jv.z*rnj, jv.w*rnj) << 16);
    di[w] = (unsigned)pk_e4m3(iv.x*rni, iv.y*rni) | ((unsigned)pk_e4m3(iv.z*rni, iv.w*rni) << 16);
    if (half == 0 && lane == 0) {
        float pos = tdot * rj * ri;
        g_pos[p] = pos;
        g_pos[p + NBATCH] = pos;
    }
}

// ---------------- kernel 2: symmetric FP8 MMA Gram + exp -> atomic rowsums ----
// Upper-triangle tiles (2080), row-major. Grid 296 = 2 CTAs/SM slot.
// Tile (I,J): row partials -> g_rowsum[I*128+r], col partials -> g_rowsum[J*128+c].
#define SMI   0
#define SMJ   32768
#define BBUF  32768
#define SMEM_TOTAL (32768 * 3)

static __device__ __forceinline__ void load_tile(unsigned dstbase, int band, int tid) {
    const char* src = (const char*)g_fp8 + (size_t)band * 128 * 256;
    #pragma unroll
    for (int i = 0; i < 8; i++) {
        int idx = tid + i * 256;
        int row = idx >> 4, u = idx & 15;
        CP_ASYNC16(dstbase + row * 256 + ((u ^ (row & 7)) << 4),
                   src + (size_t)row * 256 + u * 16);
    }
}

__global__ void __launch_bounds__(256, 2) ntx_main() {
    extern __shared__ char smem[];
    unsigned sb = smem_u32(smem);

    int tid = threadIdx.x, wid = tid >> 5, lane = tid & 31;
    int bx = blockIdx.x;
    int t0  = 7 * bx + (bx > 288 ? bx - 288 : 0);
    int cnt = 7 + (bx >= 288 ? 1 : 0);

    // decode starting (I, J) from triangular row-major index t0
    int I = (int)((129.0f - sqrtf(16641.0f - 8.0f * (float)t0)) * 0.5f);
    while (I * (129 - I) / 2 > t0) I--;
    while ((I + 1) * (128 - I) / 2 <= t0) I++;
    int J = I + (t0 - I * (129 - I) / 2);

    int wm = (wid & 1) * 64;
    int wn = (wid >> 1) * 32;
    int trow  = lane >> 2;
    int tcol2 = lane & 3;
    int sw    = lane & 7;
    int rowinA = ((lane >> 3) & 1) * 8 + (lane & 7);
    int kbA    = lane >> 4;
    int rowinB = (lane >> 4) * 8 + (lane & 7);
    int kbB    = (lane >> 3) & 1;

    unsigned abyte[4], bbyte[2];
    #pragma unroll
    for (int mt = 0; mt < 4; mt++) abyte[mt] = (unsigned)((wm + mt * 16 + rowinA) * 256);
    #pragma unroll
    for (int ng = 0; ng < 2; ng++)  bbyte[ng] = (unsigned)((wn + ng * 16 + rowinB) * 256);

    load_tile(sb + SMI, I, tid);
    load_tile(sb + SMJ, J, tid);
    CP_ASYNC_COMMIT();
    int curI = I;

    for (int k = 0; k < cnt; k++) {
        if (I != curI) {                       // band switch
            load_tile(sb + SMI, I, tid);
            CP_ASYNC_COMMIT();
            curI = I;
        }
        if (k + 1 < cnt) {                     // prefetch next J tile
            int In = I, Jn = J + 1;
            if (Jn == 64) { In = I + 1; Jn = In; }
            load_tile(sb + SMJ + (unsigned)((k + 1) & 1) * BBUF, Jn, tid);
            CP_ASYNC_COMMIT();
            asm volatile("cp.async.wait_group 1;" ::: "memory");
        } else {
            asm volatile("cp.async.wait_group 0;" ::: "memory");
        }
        __syncthreads();

        unsigned curB = sb + SMJ + (unsigned)(k & 1) * BBUF;

        // f16x2 accumulators
        unsigned acc[4][4][2];
        #pragma unroll
        for (int mt = 0; mt < 4; mt++)
            #pragma unroll
            for (int nt = 0; nt < 4; nt++) { acc[mt][nt][0] = 0u; acc[mt][nt][1] = 0u; }

        #pragma unroll
        for (int ks = 0; ks < 8; ks++) {
            unsigned koffA = (unsigned)(((ks * 2 + kbA) ^ sw) << 4);
            unsigned koffB = (unsigned)(((ks * 2 + kbB) ^ sw) << 4);
            unsigned a0[4], a1[4], a2[4], a3[4];
            #pragma unroll
            for (int mt = 0; mt < 4; mt++)
                LDSM_X4(a0[mt], a1[mt], a2[mt], a3[mt], sb + SMI + abyte[mt] + koffA);
            unsigned b0[2], b1[2], b2[2], b3[2];
            #pragma unroll
            for (int ng = 0; ng < 2; ng++)
                LDSM_X4(b0[ng], b1[ng], b2[ng], b3[ng], curB + bbyte[ng] + koffB);
            #pragma unroll
            for (int mt = 0; mt < 4; mt++) {
                MMA_FP8_H(acc[mt][0][0], acc[mt][0][1],
                          a0[mt], a1[mt], a2[mt], a3[mt], b0[0], b1[0]);
                MMA_FP8_H(acc[mt][1][0], acc[mt][1][1],
                          a0[mt], a1[mt], a2[mt], a3[mt], b2[0], b3[0]);
                MMA_FP8_H(acc[mt][2][0], acc[mt][2][1],
                          a0[mt], a1[mt], a2[mt], a3[mt], b0[1], b1[1]);
                MMA_FP8_H(acc[mt][3][0], acc[mt][3][1],
                          a0[mt], a1[mt], a2[mt], a3[mt], b2[1], b3[1]);
            }
        }

        // epilogue: exp(acc * 2/QSCALE^2), mask self-diagonal, atomic row/col sums
        bool diag = (I == J);
        float rsum[4][2], csum[4][2];
        #pragma unroll
        for (int x = 0; x < 4; x++) { rsum[x][0]=rsum[x][1]=csum[x][0]=csum[x][1]=0.f; }
        #pragma unroll
        for (int mt = 0; mt < 4; mt++) {
            int r0 = wm + mt * 16 + trow;
            #pragma unroll
            for (int nt = 0; nt < 4; nt++) {
                int c0 = wn + nt * 8 + tcol2 * 2;
                float2 lo = __half22float2(*(__half2*)&acc[mt][nt][0]);
                float2 hi = __half22float2(*(__half2*)&acc[mt][nt][1]);
                float e00 = __expf(EPSCL * lo.x);
                float e01 = __expf(EPSCL * lo.y);
                float e10 = __expf(EPSCL * hi.x);
                float e11 = __expf(EPSCL * hi.y);
                if (diag) {
                    if (r0 == c0)         e00 = 0.f;
                    if (r0 == c0 + 1)     e01 = 0.f;
                    if (r0 + 8 == c0)     e10 = 0.f;
                    if (r0 + 8 == c0 + 1) e11 = 0.f;
                }
                rsum[mt][0] += e00 + e01;
                rsum[mt][1] += e10 + e11;
                csum[nt][0] += e00 + e10;
                csum[nt][1] += e01 + e11;
            }
        }
        // row partials: reduce over n within warp, then REDG (no return)
        #pragma unroll
        for (int mt = 0; mt < 4; mt++)
            #pragma unroll
            for (int hf = 0; hf < 2; hf++) {
                float v = rsum[mt][hf];
                v += __shfl_xor_sync(0xFFFFFFFFu, v, 1);
                v += __shfl_xor_sync(0xFFFFFFFFu, v, 2);
                if ((lane & 3) == 0)
                    atomicAdd(&g_rowsum[I * 128 + wm + mt * 16 + hf * 8 + trow], v);
            }
        // col partials (symmetry): rows J*128+c, skipped on diagonal tiles
        if (!diag) {
            #pragma unroll
            for (int nt = 0; nt < 4; nt++)
                #pragma unroll
                for (int j = 0; j < 2; j++) {
                    float v = csum[nt][j];
                    v += __shfl_xor_sync(0xFFFFFFFFu, v, 4);
                    v += __shfl_xor_sync(0xFFFFFFFFu, v, 8);
                    v += __shfl_xor_sync(0xFFFFFFFFu, v, 16);
                    if (lane < 4)
                        atomicAdd(&g_rowsum[J * 128 + wn + nt * 8 + lane * 2 + j], v);
                }
        }
        __syncthreads();   // all LDSM done before next tile's loads overwrite

        // advance (I, J) row-major within upper triangle
        J++;
        if (J == 64) { I++; J = I; }
    }
}

// ---------------- kernel 3: per-row loss + last-block finalize ----------------
__global__ void ntx_fin(float* __restrict__ out) {
    __shared__ float sh[256];
    __shared__ int s_last;
    int tid = threadIdx.x;
    int i = blockIdx.x * 256 + tid;
    float rs = g_rowsum[i];
    sh[tid] = logf(rs) - INV_TEMP * g_pos[i];
    __syncthreads();
    for (int s = 128; s >= 1; s >>= 1) {
        if (tid < s) sh[tid] += sh[tid + s];
        __syncthreads();
    }
    if (tid == 0) {
        g_partial[blockIdx.x] = sh[0];
        __threadfence();
        unsigned old = atomicAdd(&g_ctr, 1u);
        s_last = (old == 31u);
    }
    __syncthreads();
    if (s_last && tid < 32) {
        float v = g_partial[tid];
        #pragma unroll
        for (int o = 16; o >= 1; o >>= 1) v += __shfl_xor_sync(0xFFFFFFFFu, v, o);
        if (tid == 0) out[0] = v / (float)TWO_N;
    }
}

extern "C" void kernel_launch(void* const* d_in, const int* in_sizes, int n_in,
                              void* d_out, int out_size) {
    const float* zis = (const float*)d_in[0];
    const float* zjs = (const float*)d_in[1];
    float* out = (float*)d_out;
    (void)in_sizes; (void)n_in; (void)out_size;

    cudaFuncSetAttribute(ntx_main, cudaFuncAttributeMaxDynamicSharedMemorySize,
                         SMEM_TOTAL);

    ntx_norm<<<NBATCH / 4, 256>>>(zis, zjs);
    ntx_main<<<296, 256, SMEM_TOTAL>>>();
    ntx_fin<<<32, 256>>>(out);
}